// round 5
// baseline (speedup 1.0000x reference)
#include <cuda_runtime.h>
#include <cuda_bf16.h>
#include <cstdint>

#define B_  8
#define C_  256
#define N_  2048
#define D_  32
#define BJ  64
#define NT  (N_ / BJ)

// ---------------------------------------------------------------------------
// Device-global scratch (allocation-free)
// ---------------------------------------------------------------------------
__device__ __nv_bfloat16  g_xt [(size_t)B_ * N_ * C_];   // x^T  (B,N,C) bf16
__device__ __nv_bfloat16  g_qt [(size_t)B_ * N_ * D_];   // q^T  (B,N,D) bf16
__device__ __nv_bfloat16  g_kt [(size_t)B_ * N_ * D_];   // k^T  (B,N,D) bf16
__device__ __nv_bfloat16  g_vbf[(size_t)B_ * C_ * N_];   // v    (B,C,N) bf16
__device__ __nv_bfloat16  g_wvbf[C_ * C_];               // wv bf16

// ---------------------------------------------------------------------------
// PTX helpers (legacy mma path only: compute_100 PTX target)
// ---------------------------------------------------------------------------
__device__ __forceinline__ uint32_t smem_u32(const void* p) {
    uint32_t a;
    asm("{ .reg .u64 t; cvta.to.shared.u64 t, %1; cvt.u32.u64 %0, t; }"
        : "=r"(a) : "l"(p));
    return a;
}
__device__ __forceinline__ void ldm_x4(uint32_t* r, uint32_t addr) {
    asm volatile("ldmatrix.sync.aligned.m8n8.x4.shared.b16 {%0,%1,%2,%3}, [%4];\n"
        : "=r"(r[0]), "=r"(r[1]), "=r"(r[2]), "=r"(r[3]) : "r"(addr));
}
__device__ __forceinline__ void mma_bf16(float* d, const uint32_t* a, const uint32_t* b) {
    asm volatile(
        "mma.sync.aligned.m16n8k16.row.col.f32.bf16.bf16.f32 "
        "{%0,%1,%2,%3},{%4,%5,%6,%7},{%8,%9},{%0,%1,%2,%3};\n"
        : "+f"(d[0]), "+f"(d[1]), "+f"(d[2]), "+f"(d[3])
        : "r"(a[0]), "r"(a[1]), "r"(a[2]), "r"(a[3]), "r"(b[0]), "r"(b[1]));
}
__device__ __forceinline__ uint32_t packbf2(float a, float b) {
    __nv_bfloat162 h = __floats2bfloat162_rn(a, b);
    return *(uint32_t*)&h;
}
#define CP_ASYNC16(saddr, gptr) \
    asm volatile("cp.async.cg.shared.global [%0], [%1], 16;\n" :: "r"(saddr), "l"(gptr))
#define CP_COMMIT() asm volatile("cp.async.commit_group;\n")
#define CP_WAIT0()  asm volatile("cp.async.wait_group 0;\n")
#define CP_WAIT1()  asm volatile("cp.async.wait_group 1;\n")

#define SMS 40   // 32 data + 8 pad bf16
#define VMS 72   // 64 data + 8 pad bf16

// legacy 64x32 warp-tile step (projv mainloop)
__device__ __forceinline__ void mma_tile_step(
    uint32_t sA, uint32_t sB, int kk, int lane, int wm, int wn, float acc[4][4][4])
{
    const int rrow  = lane & 15;
    const int chalf = (lane >> 4) << 3;
    uint32_t a[4][4], bq[2][4];
    #pragma unroll
    for (int mt = 0; mt < 4; mt++)
        ldm_x4(a[mt], sA + (uint32_t)(((wm * 64 + mt * 16 + rrow) * SMS + kk + chalf) * 2));
    #pragma unroll
    for (int np = 0; np < 2; np++)
        ldm_x4(bq[np], sB + (uint32_t)(((wn * 32 + np * 16 + rrow) * SMS + kk + chalf) * 2));
    #pragma unroll
    for (int mt = 0; mt < 4; mt++)
        #pragma unroll
        for (int nt = 0; nt < 4; nt++) {
            uint32_t bb[2] = { bq[nt >> 1][nt & 1], bq[nt >> 1][(nt & 1) + 2] };
            mma_bf16(acc[mt][nt], a[mt], bb);
        }
}

// ---------------------------------------------------------------------------
// pack_x: x (B,C,N) fp32 -> x^T (B,N,C) bf16
// ---------------------------------------------------------------------------
__global__ __launch_bounds__(256) void pack_x_kernel(
    const float* __restrict__ x, __nv_bfloat16* __restrict__ xt)
{
    __shared__ float t[32][33];
    const int b = blockIdx.z, c0 = blockIdx.y * 32, n0 = blockIdx.x * 32;
    const int tid = threadIdx.x;
    #pragma unroll
    for (int r = 0; r < 4; r++) {
        const int c = (tid >> 5) + r * 8;
        t[c][tid & 31] = x[((size_t)b * C_ + c0 + c) * N_ + n0 + (tid & 31)];
    }
    __syncthreads();
    #pragma unroll
    for (int r = 0; r < 4; r++) {
        const int n = (tid >> 5) + r * 8;
        xt[((size_t)b * N_ + n0 + n) * C_ + c0 + (tid & 31)] =
            __float2bfloat16(t[tid & 31][n]);
    }
}

__global__ __launch_bounds__(256) void pack_w_kernel(
    const float* __restrict__ w, __nv_bfloat16* __restrict__ wb, int n)
{
    const int i = blockIdx.x * 256 + threadIdx.x;
    if (i < n) wb[i] = __float2bfloat16(w[i]);
}

// ---------------------------------------------------------------------------
// Fused q+k projection (fp32 SIMT), transposed bf16 outputs (B,N,32).
// ---------------------------------------------------------------------------
__global__ __launch_bounds__(256) void projqk_kernel(
    const float* __restrict__ wq, const float* __restrict__ bq,
    const float* __restrict__ wk, const float* __restrict__ bk,
    const float* __restrict__ x,
    __nv_bfloat16* __restrict__ qt, __nv_bfloat16* __restrict__ kt)
{
    __shared__ float Ws[32][64];
    __shared__ float Xs[32][64];

    const int b = blockIdx.z, n0 = blockIdx.x * 64;
    const int tid = threadIdx.x;
    const int tr = tid >> 4, tc = tid & 15;
    const float* xb = x + (size_t)b * C_ * N_;

    float acc[4][4] = {};
    for (int c0 = 0; c0 < C_; c0 += 32) {
        {
            const int m = tid >> 2;
            const float* wrow = (m < 32) ? (wq + (size_t)m * C_)
                                         : (wk + (size_t)(m - 32) * C_);
            #pragma unroll
            for (int h = 0; h < 2; h++) {
                const int k4 = (tid & 3) * 4 + h * 16;
                const float4 w4 = *(const float4*)(wrow + c0 + k4);
                Ws[k4 + 0][m] = w4.x; Ws[k4 + 1][m] = w4.y;
                Ws[k4 + 2][m] = w4.z; Ws[k4 + 3][m] = w4.w;
            }
        }
        {
            const int kk = tid >> 3, nn = (tid & 7) * 8;
            *(float4*)&Xs[kk][nn] =
                *(const float4*)(xb + (size_t)(c0 + kk) * N_ + n0 + nn);
            *(float4*)&Xs[kk][nn + 4] =
                *(const float4*)(xb + (size_t)(c0 + kk) * N_ + n0 + nn + 4);
        }
        __syncthreads();
        #pragma unroll
        for (int kk = 0; kk < 32; kk++) {
            const float4 wf = *(const float4*)&Ws[kk][tr * 4];
            const float4 xf = *(const float4*)&Xs[kk][tc * 4];
            acc[0][0] += wf.x * xf.x; acc[0][1] += wf.x * xf.y; acc[0][2] += wf.x * xf.z; acc[0][3] += wf.x * xf.w;
            acc[1][0] += wf.y * xf.x; acc[1][1] += wf.y * xf.y; acc[1][2] += wf.y * xf.z; acc[1][3] += wf.y * xf.w;
            acc[2][0] += wf.z * xf.x; acc[2][1] += wf.z * xf.y; acc[2][2] += wf.z * xf.z; acc[2][3] += wf.z * xf.w;
            acc[3][0] += wf.w * xf.x; acc[3][1] += wf.w * xf.y; acc[3][2] += wf.w * xf.z; acc[3][3] += wf.w * xf.w;
        }
        __syncthreads();
    }

    const int mbase = tr * 4;
    const bool isq = (mbase < 32);
    __nv_bfloat16* dst = isq ? qt : kt;
    const float* bias = isq ? bq : bk;
    const int mo = isq ? mbase : (mbase - 32);
    const float b0v = bias[mo], b1v = bias[mo + 1], b2v = bias[mo + 2], b3v = bias[mo + 3];
    #pragma unroll
    for (int j = 0; j < 4; j++) {
        const int n = n0 + tc * 4 + j;
        __nv_bfloat16* o = dst + ((size_t)b * N_ + n) * D_ + mo;
        *(__nv_bfloat162*)(o)     = __floats2bfloat162_rn(acc[0][j] + b0v, acc[1][j] + b1v);
        *(__nv_bfloat162*)(o + 2) = __floats2bfloat162_rn(acc[2][j] + b2v, acc[3][j] + b3v);
    }
}

// ---------------------------------------------------------------------------
// v projection (tensor core)
// ---------------------------------------------------------------------------
__global__ __launch_bounds__(256) void projv_tc(
    const __nv_bfloat16* __restrict__ wv, const float* __restrict__ bv,
    const __nv_bfloat16* __restrict__ xt, __nv_bfloat16* __restrict__ v)
{
    __shared__ __align__(16) __nv_bfloat16 sm[4 * 128 * SMS];
    const int b = blockIdx.z, m0 = blockIdx.y * 128, n0 = blockIdx.x * 128;
    const int tid = threadIdx.x, lane = tid & 31, warp = tid >> 5;
    const int wm = warp & 1, wn = warp >> 1;
    const uint32_t sbase = smem_u32(sm);
    const int row = tid >> 2, c8 = (tid & 3) << 3;

    const __nv_bfloat16* A = wv + (size_t)(m0 + row) * C_ + c8;
    const __nv_bfloat16* Bm = xt + ((size_t)b * N_ + n0 + row) * C_ + c8;

    float acc[4][4][4] = {};
    {
        const uint32_t sa = sbase + (uint32_t)((row * SMS + c8) * 2);
        CP_ASYNC16(sa,                        A);
        CP_ASYNC16(sa + 64 * SMS * 2,         A + (size_t)64 * C_);
        CP_ASYNC16(sa + 128 * SMS * 2,        Bm);
        CP_ASYNC16(sa + (128 + 64) * SMS * 2, Bm + (size_t)64 * C_);
        CP_COMMIT();
    }
    #pragma unroll 1
    for (int it = 0; it < 8; it++) {
        CP_WAIT0(); __syncthreads();
        if (it < 7) {
            const int st = (it + 1) & 1, j0 = (it + 1) * 32;
            const uint32_t sa = sbase + (uint32_t)(st * 2 * 128 * SMS * 2 + (row * SMS + c8) * 2);
            CP_ASYNC16(sa,                        A + j0);
            CP_ASYNC16(sa + 64 * SMS * 2,         A + j0 + (size_t)64 * C_);
            CP_ASYNC16(sa + 128 * SMS * 2,        Bm + j0);
            CP_ASYNC16(sa + (128 + 64) * SMS * 2, Bm + j0 + (size_t)64 * C_);
            CP_COMMIT();
        }
        const uint32_t sA = sbase + (uint32_t)((it & 1) * 2 * 128 * SMS * 2);
        const uint32_t sB = sA + 128 * SMS * 2;
        mma_tile_step(sA, sB, 0,  lane, wm, wn, acc);
        mma_tile_step(sA, sB, 16, lane, wm, wn, acc);
        __syncthreads();
    }
    #pragma unroll
    for (int mt = 0; mt < 4; mt++)
        #pragma unroll
        for (int h = 0; h < 2; h++) {
            const int m = m0 + wm * 64 + mt * 16 + (lane >> 2) + h * 8;
            const float bm = bv[m];
            #pragma unroll
            for (int nt = 0; nt < 4; nt++) {
                const int n = n0 + wn * 32 + nt * 8 + ((lane & 3) << 1);
                __nv_bfloat162 o;
                o.x = __float2bfloat16(acc[mt][nt][h * 2 + 0] + bm);
                o.y = __float2bfloat16(acc[mt][nt][h * 2 + 1] + bm);
                *(__nv_bfloat162*)(v + ((size_t)b * C_ + m) * N_ + n) = o;
            }
        }
}

// ---------------------------------------------------------------------------
// Flash attention, no-max softmax (logits bounded: q.k over 32 dims, |S|<~40).
// Block: 128 i-rows x 128 c-chunk, 8 warps, BJ=64, triple-buffered K/V.
// SMEM 80896B -> 2 blocks/SM. grid = (C/128, N/128, B).
// ---------------------------------------------------------------------------
#define FL_KOFF (128 * SMS)                 // after Q
#define FL_VOFF (FL_KOFF + 3 * 64 * SMS)    // after 3 K bufs
#define FL_SMEM ((FL_VOFF + 3 * 128 * VMS) * 2)   // bytes = 80896

__global__ __launch_bounds__(256, 2) void flash_tc(
    const __nv_bfloat16* __restrict__ qt, const __nv_bfloat16* __restrict__ kt,
    const __nv_bfloat16* __restrict__ v, const float* __restrict__ x,
    const float* __restrict__ gamma, float* __restrict__ out)
{
    extern __shared__ __align__(16) char smem_raw[];
    __nv_bfloat16* sQ = (__nv_bfloat16*)smem_raw;
    float* sO = (float*)smem_raw;            // epilogue reuse (64 x 132 fp32)

    const int b  = blockIdx.z;
    const int i0 = blockIdx.y * 128;
    const int c0 = blockIdx.x * 128;
    const int tid = threadIdx.x, lane = tid & 31, warp = tid >> 5;
    const int rrow = lane & 15, chalf = (lane >> 4) << 3;

    const __nv_bfloat16* Qg = qt + ((size_t)b * N_ + i0) * D_;
    const __nv_bfloat16* Kg = kt + (size_t)b * N_ * D_;
    const __nv_bfloat16* Vg = v  + ((size_t)b * C_ + c0) * N_;

    const uint32_t sQa = smem_u32(sQ);
    const uint32_t sKa = sQa + FL_KOFF * 2;
    const uint32_t sVa = sQa + FL_VOFF * 2;

    // prologue: group0 = {Q, K0, V0}, group1 = {K1, V1}
    {
        #pragma unroll
        for (int p = 0; p < 2; p++) {
            const int idx = tid + p * 256, r = idx >> 2, s = (idx & 3) * 8;
            CP_ASYNC16(sQa + (uint32_t)((r * SMS + s) * 2), Qg + (size_t)r * D_ + s);
        }
        { const int r = tid >> 2, s = (tid & 3) * 8;
          CP_ASYNC16(sKa + (uint32_t)((r * SMS + s) * 2), Kg + (size_t)r * D_ + s); }
        #pragma unroll
        for (int p = 0; p < 4; p++) {
            const int idx = tid + p * 256, r = idx >> 3, s = (idx & 7) * 8;
            CP_ASYNC16(sVa + (uint32_t)((r * VMS + s) * 2), Vg + (size_t)r * N_ + s);
        }
        CP_COMMIT();
        { const int r = tid >> 2, s = (tid & 3) * 8;
          CP_ASYNC16(sKa + (uint32_t)((64 * SMS + r * SMS + s) * 2),
                     Kg + (size_t)(BJ + r) * D_ + s); }
        #pragma unroll
        for (int p = 0; p < 4; p++) {
            const int idx = tid + p * 256, r = idx >> 3, s = (idx & 7) * 8;
            CP_ASYNC16(sVa + (uint32_t)((128 * VMS + r * VMS + s) * 2),
                       Vg + (size_t)r * N_ + BJ + s);
        }
        CP_COMMIT();
    }

    float accO[16][4] = {};
    float l0 = 0.f, l1 = 0.f;
    uint32_t qf[2][4];

    #pragma unroll 1
    for (int t = 0; t < NT; t++) {
        CP_WAIT1(); __syncthreads();   // tile t resident
        if (t == 0) {
            ldm_x4(qf[0], sQa + (uint32_t)(((warp * 16 + rrow) * SMS + 0  + chalf) * 2));
            ldm_x4(qf[1], sQa + (uint32_t)(((warp * 16 + rrow) * SMS + 16 + chalf) * 2));
        }
        // prefetch tile t+2 (always commit one group to keep WAIT1 semantics)
        if (t + 2 < NT) {
            const int bf = (t + 2) % 3, j1 = (t + 2) * BJ;
            { const int r = tid >> 2, s = (tid & 3) * 8;
              CP_ASYNC16(sKa + (uint32_t)((bf * 64 * SMS + r * SMS + s) * 2),
                         Kg + (size_t)(j1 + r) * D_ + s); }
            #pragma unroll
            for (int p = 0; p < 4; p++) {
                const int idx = tid + p * 256, r = idx >> 3, s = (idx & 7) * 8;
                CP_ASYNC16(sVa + (uint32_t)((bf * 128 * VMS + r * VMS + s) * 2),
                           Vg + (size_t)r * N_ + j1 + s);
            }
        }
        CP_COMMIT();

        const uint32_t kb = sKa + (uint32_t)((t % 3) * 64 * SMS * 2);
        const uint32_t vb = sVa + (uint32_t)((t % 3) * 128 * VMS * 2);

        // ---- S = Q K^T (warp: 16i x 64j) ----
        float accS[8][4] = {};
        #pragma unroll
        for (int jt = 0; jt < 4; jt++) {
            uint32_t b0[4], b1[4];
            ldm_x4(b0, kb + (uint32_t)(((jt * 16 + rrow) * SMS + 0  + chalf) * 2));
            ldm_x4(b1, kb + (uint32_t)(((jt * 16 + rrow) * SMS + 16 + chalf) * 2));
            #pragma unroll
            for (int np = 0; np < 2; np++) {
                uint32_t bb0[2] = { b0[np], b0[np + 2] };
                uint32_t bb1[2] = { b1[np], b1[np + 2] };
                mma_bf16(accS[jt * 2 + np], qf[0], bb0);
                mma_bf16(accS[jt * 2 + np], qf[1], bb1);
            }
        }

        // ---- exp (no max subtraction; logits bounded) + pack bf16 ----
        uint32_t pf[4][4];
        #pragma unroll
        for (int t8 = 0; t8 < 8; t8++) {
            const float p0 = __expf(accS[t8][0]);
            const float p1 = __expf(accS[t8][1]);
            const float p2 = __expf(accS[t8][2]);
            const float p3 = __expf(accS[t8][3]);
            l0 += p0 + p1; l1 += p2 + p3;
            const int ks = t8 >> 1;
            if ((t8 & 1) == 0) { pf[ks][0] = packbf2(p0, p1); pf[ks][1] = packbf2(p2, p3); }
            else               { pf[ks][2] = packbf2(p0, p1); pf[ks][3] = packbf2(p2, p3); }
        }

        // ---- O += P V^T (warp: 16i x 128c, k=64) ----
        #pragma unroll
        for (int ks = 0; ks < 4; ks++) {
            #pragma unroll
            for (int cg = 0; cg < 8; cg++) {
                uint32_t vb4[4];
                ldm_x4(vb4, vb + (uint32_t)(((cg * 16 + rrow) * VMS + ks * 16 + chalf) * 2));
                #pragma unroll
                for (int np = 0; np < 2; np++) {
                    uint32_t bb[2] = { vb4[np], vb4[np + 2] };
                    mma_bf16(accO[cg * 2 + np], pf[ks], bb);
                }
            }
        }
    }

    // ---- epilogue: reduce l across quad, normalize, 2-pass transpose ----
    l0 += __shfl_xor_sync(0xFFFFFFFFu, l0, 1);
    l0 += __shfl_xor_sync(0xFFFFFFFFu, l0, 2);
    l1 += __shfl_xor_sync(0xFFFFFFFFu, l1, 1);
    l1 += __shfl_xor_sync(0xFFFFFFFFu, l1, 2);
    const float il0 = 1.f / l0, il1 = 1.f / l1;
    const float g = *gamma;

    #pragma unroll 1
    for (int pass = 0; pass < 2; pass++) {
        __syncthreads();
        #pragma unroll
        for (int t8 = 0; t8 < 8; t8++) {
            const int t = pass * 8 + t8;
            const int c = t8 * 8 + (lane & 3) * 2;       // 0..63 local
            const int i = warp * 16 + (lane >> 2);
            sO[(size_t)c * 132 + i]           = accO[t][0] * il0;
            sO[(size_t)(c + 1) * 132 + i]     = accO[t][1] * il0;
            sO[(size_t)c * 132 + i + 8]       = accO[t][2] * il1;
            sO[(size_t)(c + 1) * 132 + i + 8] = accO[t][3] * il1;
        }
        __syncthreads();
        #pragma unroll
        for (int rep = 0; rep < 8; rep++) {
            const int idx = rep * 256 + tid;
            const int c = idx >> 5, i4 = (idx & 31) * 4;
            const size_t base = ((size_t)b * C_ + c0 + pass * 64 + c) * N_ + i0 + i4;
            const float4 xv = *(const float4*)(x + base);
            const float4 ov = *(const float4*)&sO[(size_t)c * 132 + i4];
            float4 o;
            o.x = g * ov.x + xv.x; o.y = g * ov.y + xv.y;
            o.z = g * ov.z + xv.z; o.w = g * ov.w + xv.w;
            *(float4*)(out + base) = o;
        }
    }
}

// ---------------------------------------------------------------------------
// Launch
// ---------------------------------------------------------------------------
extern "C" void kernel_launch(void* const* d_in, const int* in_sizes, int n_in,
                              void* d_out, int out_size)
{
    const float* x     = (const float*)d_in[0];
    const float* wq    = (const float*)d_in[1];
    const float* bq    = (const float*)d_in[2];
    const float* wk    = (const float*)d_in[3];
    const float* bk    = (const float*)d_in[4];
    const float* wv    = (const float*)d_in[5];
    const float* bv    = (const float*)d_in[6];
    const float* gamma = (const float*)d_in[7];
    float* out = (float*)d_out;

    __nv_bfloat16 *pxt, *pqt, *pkt, *pvbf, *pwvbf;
    cudaGetSymbolAddress((void**)&pxt,   g_xt);
    cudaGetSymbolAddress((void**)&pqt,   g_qt);
    cudaGetSymbolAddress((void**)&pkt,   g_kt);
    cudaGetSymbolAddress((void**)&pvbf,  g_vbf);
    cudaGetSymbolAddress((void**)&pwvbf, g_wvbf);

    static bool attr_set = false;
    if (!attr_set) {
        cudaFuncSetAttribute(flash_tc, cudaFuncAttributeMaxDynamicSharedMemorySize,
                             FL_SMEM);
        attr_set = true;
    }

    pack_x_kernel<<<dim3(N_ / 32, C_ / 32, B_), 256>>>(x, pxt);
    pack_w_kernel<<<(C_ * C_ + 255) / 256, 256>>>(wv, pwvbf, C_ * C_);

    projqk_kernel<<<dim3(N_ / 64, 1, B_), 256>>>(wq, bq, wk, bk, x, pqt, pkt);
    projv_tc<<<dim3(N_ / 128, C_ / 128, B_), 256>>>(pwvbf, bv, pxt, pvbf);

    flash_tc<<<dim3(C_ / 128, N_ / 128, B_), 256, FL_SMEM>>>(pqt, pkt, pvbf, x, gamma, out);
}

// round 6
// speedup vs baseline: 1.2456x; 1.2456x over previous
#include <cuda_runtime.h>
#include <cuda_bf16.h>
#include <cstdint>

#define B_  8
#define C_  256
#define N_  2048
#define D_  32
#define BJ  64
#define NT  (N_ / BJ)

// ---------------------------------------------------------------------------
// Device-global scratch (allocation-free)
// ---------------------------------------------------------------------------
__device__ __nv_bfloat16  g_xt [(size_t)B_ * N_ * C_];   // x^T  (B,N,C) bf16
__device__ __nv_bfloat16  g_qt [(size_t)B_ * N_ * D_];   // q^T  (B,N,D) bf16
__device__ __nv_bfloat16  g_kt [(size_t)B_ * N_ * D_];   // k^T  (B,N,D) bf16
__device__ __nv_bfloat16  g_vbf[(size_t)B_ * C_ * N_];   // v    (B,C,N) bf16
__device__ __nv_bfloat16  g_wvbf[C_ * C_];               // wv bf16

// ---------------------------------------------------------------------------
// PTX helpers (legacy mma path: compute_100 PTX target, no tcgen05)
// ---------------------------------------------------------------------------
__device__ __forceinline__ uint32_t smem_u32(const void* p) {
    uint32_t a;
    asm("{ .reg .u64 t; cvta.to.shared.u64 t, %1; cvt.u32.u64 %0, t; }"
        : "=r"(a) : "l"(p));
    return a;
}
__device__ __forceinline__ void ldm_x4(uint32_t* r, uint32_t addr) {
    asm volatile("ldmatrix.sync.aligned.m8n8.x4.shared.b16 {%0,%1,%2,%3}, [%4];\n"
        : "=r"(r[0]), "=r"(r[1]), "=r"(r[2]), "=r"(r[3]) : "r"(addr));
}
__device__ __forceinline__ void mma_bf16(float* d, const uint32_t* a, const uint32_t* b) {
    asm volatile(
        "mma.sync.aligned.m16n8k16.row.col.f32.bf16.bf16.f32 "
        "{%0,%1,%2,%3},{%4,%5,%6,%7},{%8,%9},{%0,%1,%2,%3};\n"
        : "+f"(d[0]), "+f"(d[1]), "+f"(d[2]), "+f"(d[3])
        : "r"(a[0]), "r"(a[1]), "r"(a[2]), "r"(a[3]), "r"(b[0]), "r"(b[1]));
}
__device__ __forceinline__ uint32_t packbf2(float a, float b) {
    __nv_bfloat162 h = __floats2bfloat162_rn(a, b);
    return *(uint32_t*)&h;
}
#define CP_ASYNC16(saddr, gptr) \
    asm volatile("cp.async.cg.shared.global [%0], [%1], 16;\n" :: "r"(saddr), "l"(gptr))
#define CP_COMMIT() asm volatile("cp.async.commit_group;\n")
#define CP_WAIT0()  asm volatile("cp.async.wait_group 0;\n")
#define CP_WAIT1()  asm volatile("cp.async.wait_group 1;\n")
#define BAR_SYNC(id, cnt) \
    asm volatile("bar.sync %0, %1;" :: "r"(id), "r"(cnt) : "memory")

#define SMS 40   // 32 data + 8 pad bf16
#define VMS 72   // 64 data + 8 pad bf16

// legacy 64x32 warp-tile step (projv mainloop)
__device__ __forceinline__ void mma_tile_step(
    uint32_t sA, uint32_t sB, int kk, int lane, int wm, int wn, float acc[4][4][4])
{
    const int rrow  = lane & 15;
    const int chalf = (lane >> 4) << 3;
    uint32_t a[4][4], bq[2][4];
    #pragma unroll
    for (int mt = 0; mt < 4; mt++)
        ldm_x4(a[mt], sA + (uint32_t)(((wm * 64 + mt * 16 + rrow) * SMS + kk + chalf) * 2));
    #pragma unroll
    for (int np = 0; np < 2; np++)
        ldm_x4(bq[np], sB + (uint32_t)(((wn * 32 + np * 16 + rrow) * SMS + kk + chalf) * 2));
    #pragma unroll
    for (int mt = 0; mt < 4; mt++)
        #pragma unroll
        for (int nt = 0; nt < 4; nt++) {
            uint32_t bb[2] = { bq[nt >> 1][nt & 1], bq[nt >> 1][(nt & 1) + 2] };
            mma_bf16(acc[mt][nt], a[mt], bb);
        }
}

// ---------------------------------------------------------------------------
// pack_x: x (B,C,N) fp32 -> x^T (B,N,C) bf16
// ---------------------------------------------------------------------------
__global__ __launch_bounds__(256) void pack_x_kernel(
    const float* __restrict__ x, __nv_bfloat16* __restrict__ xt)
{
    __shared__ float t[32][33];
    const int b = blockIdx.z, c0 = blockIdx.y * 32, n0 = blockIdx.x * 32;
    const int tid = threadIdx.x;
    #pragma unroll
    for (int r = 0; r < 4; r++) {
        const int c = (tid >> 5) + r * 8;
        t[c][tid & 31] = x[((size_t)b * C_ + c0 + c) * N_ + n0 + (tid & 31)];
    }
    __syncthreads();
    #pragma unroll
    for (int r = 0; r < 4; r++) {
        const int n = (tid >> 5) + r * 8;
        xt[((size_t)b * N_ + n0 + n) * C_ + c0 + (tid & 31)] =
            __float2bfloat16(t[tid & 31][n]);
    }
}

__global__ __launch_bounds__(256) void pack_w_kernel(
    const float* __restrict__ w, __nv_bfloat16* __restrict__ wb, int n)
{
    const int i = blockIdx.x * 256 + threadIdx.x;
    if (i < n) wb[i] = __float2bfloat16(w[i]);
}

// ---------------------------------------------------------------------------
// Fused q+k projection (fp32 SIMT), transposed bf16 outputs (B,N,32).
// ---------------------------------------------------------------------------
__global__ __launch_bounds__(256) void projqk_kernel(
    const float* __restrict__ wq, const float* __restrict__ bq,
    const float* __restrict__ wk, const float* __restrict__ bk,
    const float* __restrict__ x,
    __nv_bfloat16* __restrict__ qt, __nv_bfloat16* __restrict__ kt)
{
    __shared__ float Ws[32][64];
    __shared__ float Xs[32][64];

    const int b = blockIdx.z, n0 = blockIdx.x * 64;
    const int tid = threadIdx.x;
    const int tr = tid >> 4, tc = tid & 15;
    const float* xb = x + (size_t)b * C_ * N_;

    float acc[4][4] = {};
    for (int c0 = 0; c0 < C_; c0 += 32) {
        {
            const int m = tid >> 2;
            const float* wrow = (m < 32) ? (wq + (size_t)m * C_)
                                         : (wk + (size_t)(m - 32) * C_);
            #pragma unroll
            for (int h = 0; h < 2; h++) {
                const int k4 = (tid & 3) * 4 + h * 16;
                const float4 w4 = *(const float4*)(wrow + c0 + k4);
                Ws[k4 + 0][m] = w4.x; Ws[k4 + 1][m] = w4.y;
                Ws[k4 + 2][m] = w4.z; Ws[k4 + 3][m] = w4.w;
            }
        }
        {
            const int kk = tid >> 3, nn = (tid & 7) * 8;
            *(float4*)&Xs[kk][nn] =
                *(const float4*)(xb + (size_t)(c0 + kk) * N_ + n0 + nn);
            *(float4*)&Xs[kk][nn + 4] =
                *(const float4*)(xb + (size_t)(c0 + kk) * N_ + n0 + nn + 4);
        }
        __syncthreads();
        #pragma unroll
        for (int kk = 0; kk < 32; kk++) {
            const float4 wf = *(const float4*)&Ws[kk][tr * 4];
            const float4 xf = *(const float4*)&Xs[kk][tc * 4];
            acc[0][0] += wf.x * xf.x; acc[0][1] += wf.x * xf.y; acc[0][2] += wf.x * xf.z; acc[0][3] += wf.x * xf.w;
            acc[1][0] += wf.y * xf.x; acc[1][1] += wf.y * xf.y; acc[1][2] += wf.y * xf.z; acc[1][3] += wf.y * xf.w;
            acc[2][0] += wf.z * xf.x; acc[2][1] += wf.z * xf.y; acc[2][2] += wf.z * xf.z; acc[2][3] += wf.z * xf.w;
            acc[3][0] += wf.w * xf.x; acc[3][1] += wf.w * xf.y; acc[3][2] += wf.w * xf.z; acc[3][3] += wf.w * xf.w;
        }
        __syncthreads();
    }

    const int mbase = tr * 4;
    const bool isq = (mbase < 32);
    __nv_bfloat16* dst = isq ? qt : kt;
    const float* bias = isq ? bq : bk;
    const int mo = isq ? mbase : (mbase - 32);
    const float b0v = bias[mo], b1v = bias[mo + 1], b2v = bias[mo + 2], b3v = bias[mo + 3];
    #pragma unroll
    for (int j = 0; j < 4; j++) {
        const int n = n0 + tc * 4 + j;
        __nv_bfloat16* o = dst + ((size_t)b * N_ + n) * D_ + mo;
        *(__nv_bfloat162*)(o)     = __floats2bfloat162_rn(acc[0][j] + b0v, acc[1][j] + b1v);
        *(__nv_bfloat162*)(o + 2) = __floats2bfloat162_rn(acc[2][j] + b2v, acc[3][j] + b3v);
    }
}

// ---------------------------------------------------------------------------
// v projection (tensor core)
// ---------------------------------------------------------------------------
__global__ __launch_bounds__(256) void projv_tc(
    const __nv_bfloat16* __restrict__ wv, const float* __restrict__ bv,
    const __nv_bfloat16* __restrict__ xt, __nv_bfloat16* __restrict__ v)
{
    __shared__ __align__(16) __nv_bfloat16 sm[4 * 128 * SMS];
    const int b = blockIdx.z, m0 = blockIdx.y * 128, n0 = blockIdx.x * 128;
    const int tid = threadIdx.x, lane = tid & 31, warp = tid >> 5;
    const int wm = warp & 1, wn = warp >> 1;
    const uint32_t sbase = smem_u32(sm);
    const int row = tid >> 2, c8 = (tid & 3) << 3;

    const __nv_bfloat16* A = wv + (size_t)(m0 + row) * C_ + c8;
    const __nv_bfloat16* Bm = xt + ((size_t)b * N_ + n0 + row) * C_ + c8;

    float acc[4][4][4] = {};
    {
        const uint32_t sa = sbase + (uint32_t)((row * SMS + c8) * 2);
        CP_ASYNC16(sa,                        A);
        CP_ASYNC16(sa + 64 * SMS * 2,         A + (size_t)64 * C_);
        CP_ASYNC16(sa + 128 * SMS * 2,        Bm);
        CP_ASYNC16(sa + (128 + 64) * SMS * 2, Bm + (size_t)64 * C_);
        CP_COMMIT();
    }
    #pragma unroll 1
    for (int it = 0; it < 8; it++) {
        CP_WAIT0(); __syncthreads();
        if (it < 7) {
            const int st = (it + 1) & 1, j0 = (it + 1) * 32;
            const uint32_t sa = sbase + (uint32_t)(st * 2 * 128 * SMS * 2 + (row * SMS + c8) * 2);
            CP_ASYNC16(sa,                        A + j0);
            CP_ASYNC16(sa + 64 * SMS * 2,         A + j0 + (size_t)64 * C_);
            CP_ASYNC16(sa + 128 * SMS * 2,        Bm + j0);
            CP_ASYNC16(sa + (128 + 64) * SMS * 2, Bm + j0 + (size_t)64 * C_);
            CP_COMMIT();
        }
        const uint32_t sA = sbase + (uint32_t)((it & 1) * 2 * 128 * SMS * 2);
        const uint32_t sB = sA + 128 * SMS * 2;
        mma_tile_step(sA, sB, 0,  lane, wm, wn, acc);
        mma_tile_step(sA, sB, 16, lane, wm, wn, acc);
        __syncthreads();
    }
    #pragma unroll
    for (int mt = 0; mt < 4; mt++)
        #pragma unroll
        for (int h = 0; h < 2; h++) {
            const int m = m0 + wm * 64 + mt * 16 + (lane >> 2) + h * 8;
            const float bm = bv[m];
            #pragma unroll
            for (int nt = 0; nt < 4; nt++) {
                const int n = n0 + wn * 32 + nt * 8 + ((lane & 3) << 1);
                __nv_bfloat162 o;
                o.x = __float2bfloat16(acc[mt][nt][h * 2 + 0] + bm);
                o.y = __float2bfloat16(acc[mt][nt][h * 2 + 1] + bm);
                *(__nv_bfloat162*)(v + ((size_t)b * C_ + m) * N_ + n) = o;
            }
        }
}

// ---------------------------------------------------------------------------
// Flash attention (no-max softmax; logits bounded: q.k over 32 dims).
// Block = 64 i-rows x 128 c, 8 warps = 4 i-slices x 2 halves.
//   S phase: warp computes its i-slice x its j-half (16x32, 8 mma), exps,
//            stores P to a per-pair smem tile; pair bar.sync; both warps
//            ldmatrix the full 16x64 P as A-operand.
//   O phase: warp accumulates 16i x 64c (its c-half), k=64: 32 mma.
// accO = 32 regs -> fits 2 CTAs/SM without spills. grid (2,32,8) = 512 blocks
// = exactly 2 full waves at 2 blocks/SM. Triple-buffered K/V cp.async.
// ---------------------------------------------------------------------------
#define QOFF_B  0
#define KOFF_B  (64 * SMS * 2)                       // 5120
#define VOFF_B  (KOFF_B + 3 * 64 * SMS * 2)          // 20480
#define POFF_B  (VOFF_B + 3 * 128 * VMS * 2)         // 75776
#define PPITCH  (16 * VMS * 2)                       // 2304 bytes per pair tile
#define FL_SMEM (POFF_B + 4 * PPITCH)                // 84992

__global__ __launch_bounds__(256, 2) void flash_tc(
    const __nv_bfloat16* __restrict__ qt, const __nv_bfloat16* __restrict__ kt,
    const __nv_bfloat16* __restrict__ v, const float* __restrict__ x,
    const float* __restrict__ gamma, float* __restrict__ out)
{
    extern __shared__ __align__(16) char smem_raw[];
    __shared__ float l_sm[2][64];

    const int b  = blockIdx.z;
    const int i0 = blockIdx.y * 64;
    const int c0 = blockIdx.x * 128;
    const int tid = threadIdx.x, lane = tid & 31, warp = tid >> 5;
    const int islice = warp >> 1;        // 0..3: i-rows islice*16..+16
    const int half   = warp & 1;         // j-half in S phase, c-half in O phase
    const int rrow = lane & 15, chalf = (lane >> 4) << 3;

    const __nv_bfloat16* Qg = qt + ((size_t)b * N_ + i0) * D_;
    const __nv_bfloat16* Kg = kt + (size_t)b * N_ * D_;
    const __nv_bfloat16* Vg = v  + ((size_t)b * C_ + c0) * N_;

    const uint32_t sQa = smem_u32(smem_raw);
    const uint32_t sKa = sQa + KOFF_B;
    const uint32_t sVa = sQa + VOFF_B;
    const uint32_t sPa = sQa + POFF_B + (uint32_t)islice * PPITCH;

    // prologue: group0 = {Q, K0, V0}, group1 = {K1, V1}
    {
        const int r = tid >> 2, s = (tid & 3) * 8;
        CP_ASYNC16(sQa + (uint32_t)((r * SMS + s) * 2), Qg + (size_t)r * D_ + s);
        CP_ASYNC16(sKa + (uint32_t)((r * SMS + s) * 2), Kg + (size_t)r * D_ + s);
        #pragma unroll
        for (int p = 0; p < 4; p++) {
            const int idx = tid + p * 256, vr = idx >> 3, vs = (idx & 7) * 8;
            CP_ASYNC16(sVa + (uint32_t)((vr * VMS + vs) * 2), Vg + (size_t)vr * N_ + vs);
        }
        CP_COMMIT();
        CP_ASYNC16(sKa + (uint32_t)((64 * SMS + r * SMS + s) * 2),
                   Kg + (size_t)(BJ + r) * D_ + s);
        #pragma unroll
        for (int p = 0; p < 4; p++) {
            const int idx = tid + p * 256, vr = idx >> 3, vs = (idx & 7) * 8;
            CP_ASYNC16(sVa + (uint32_t)((128 * VMS + vr * VMS + vs) * 2),
                       Vg + (size_t)vr * N_ + BJ + vs);
        }
        CP_COMMIT();
    }

    float accO[8][4] = {};
    float l0 = 0.f, l1 = 0.f;
    uint32_t qf[2][4];

    #pragma unroll 1
    for (int t = 0; t < NT; t++) {
        CP_WAIT1(); __syncthreads();     // tile t resident
        if (t == 0) {
            ldm_x4(qf[0], sQa + (uint32_t)(((islice * 16 + rrow) * SMS + 0  + chalf) * 2));
            ldm_x4(qf[1], sQa + (uint32_t)(((islice * 16 + rrow) * SMS + 16 + chalf) * 2));
        }
        // prefetch tile t+2 (always commit a group to keep WAIT1 accounting)
        if (t + 2 < NT) {
            const int bf = (t + 2) % 3, j1 = (t + 2) * BJ;
            const int r = tid >> 2, s = (tid & 3) * 8;
            CP_ASYNC16(sKa + (uint32_t)((bf * 64 * SMS + r * SMS + s) * 2),
                       Kg + (size_t)(j1 + r) * D_ + s);
            #pragma unroll
            for (int p = 0; p < 4; p++) {
                const int idx = tid + p * 256, vr = idx >> 3, vs = (idx & 7) * 8;
                CP_ASYNC16(sVa + (uint32_t)((bf * 128 * VMS + vr * VMS + vs) * 2),
                           Vg + (size_t)vr * N_ + j1 + vs);
            }
        }
        CP_COMMIT();

        const uint32_t kb = sKa + (uint32_t)((t % 3) * 64 * SMS * 2);
        const uint32_t vb = sVa + (uint32_t)((t % 3) * 128 * VMS * 2);

        // ---- S = Q K^T : warp computes 16i x 32j (its j-half) ----
        float accS[4][4] = {};
        #pragma unroll
        for (int jt2 = 0; jt2 < 2; jt2++) {
            const int jt = half * 2 + jt2;
            uint32_t b0[4], b1[4];
            ldm_x4(b0, kb + (uint32_t)(((jt * 16 + rrow) * SMS + 0  + chalf) * 2));
            ldm_x4(b1, kb + (uint32_t)(((jt * 16 + rrow) * SMS + 16 + chalf) * 2));
            #pragma unroll
            for (int np = 0; np < 2; np++) {
                uint32_t bb0[2] = { b0[np], b0[np + 2] };
                uint32_t bb1[2] = { b1[np], b1[np + 2] };
                mma_bf16(accS[jt2 * 2 + np], qf[0], bb0);
                mma_bf16(accS[jt2 * 2 + np], qf[1], bb1);
            }
        }

        // ---- exp (no max) + store P half to pair tile + partial l ----
        #pragma unroll
        for (int t4 = 0; t4 < 4; t4++) {
            const float e0 = __expf(accS[t4][0]);
            const float e1 = __expf(accS[t4][1]);
            const float e2 = __expf(accS[t4][2]);
            const float e3 = __expf(accS[t4][3]);
            l0 += e0 + e1; l1 += e2 + e3;
            const int jcol = half * 32 + t4 * 8 + (lane & 3) * 2;
            const int r0 = lane >> 2;
            *(uint32_t*)(smem_raw + POFF_B + islice * PPITCH + (r0 * VMS + jcol) * 2)
                = packbf2(e0, e1);
            *(uint32_t*)(smem_raw + POFF_B + islice * PPITCH + ((r0 + 8) * VMS + jcol) * 2)
                = packbf2(e2, e3);
        }
        BAR_SYNC(1 + islice, 64);   // pair barrier: P tile complete

        // ---- load full P (16i x 64j) as A-operand fragments ----
        uint32_t pf[4][4];
        #pragma unroll
        for (int ks = 0; ks < 4; ks++)
            ldm_x4(pf[ks], sPa + (uint32_t)(((rrow) * VMS + ks * 16 + chalf) * 2));

        // ---- O += P V^T : warp 16i x 64c (its c-half), k=64 ----
        #pragma unroll
        for (int ks = 0; ks < 4; ks++) {
            #pragma unroll
            for (int cg = 0; cg < 4; cg++) {
                uint32_t vb4[4];
                ldm_x4(vb4, vb + (uint32_t)(((half * 64 + cg * 16 + rrow) * VMS
                                             + ks * 16 + chalf) * 2));
                #pragma unroll
                for (int np = 0; np < 2; np++) {
                    uint32_t bb[2] = { vb4[np], vb4[np + 2] };
                    mma_bf16(accO[cg * 2 + np], pf[ks], bb);
                }
            }
        }
    }

    // ---- epilogue ----
    // l: quad-reduce, then combine j-halves via smem
    l0 += __shfl_xor_sync(0xFFFFFFFFu, l0, 1);
    l0 += __shfl_xor_sync(0xFFFFFFFFu, l0, 2);
    l1 += __shfl_xor_sync(0xFFFFFFFFu, l1, 1);
    l1 += __shfl_xor_sync(0xFFFFFFFFu, l1, 2);
    if ((lane & 3) == 0) {
        l_sm[half][islice * 16 + (lane >> 2)]     = l0;
        l_sm[half][islice * 16 + (lane >> 2) + 8] = l1;
    }
    __syncthreads();   // also quiesces all smem reads before sO overwrite

    const int r = islice * 16 + (lane >> 2);
    const float il0 = 1.f / (l_sm[0][r] + l_sm[1][r]);
    const float il1 = 1.f / (l_sm[0][r + 8] + l_sm[1][r + 8]);
    const float g = *gamma;
    float* sO = (float*)smem_raw;   // 128c x 68i fp32 = 34816B, K/V/P dead

    #pragma unroll
    for (int t8 = 0; t8 < 8; t8++) {
        const int c = half * 64 + t8 * 8 + (lane & 3) * 2;
        const int i = islice * 16 + (lane >> 2);
        sO[(size_t)c * 68 + i]           = accO[t8][0] * il0;
        sO[(size_t)(c + 1) * 68 + i]     = accO[t8][1] * il0;
        sO[(size_t)c * 68 + i + 8]       = accO[t8][2] * il1;
        sO[(size_t)(c + 1) * 68 + i + 8] = accO[t8][3] * il1;
    }
    __syncthreads();
    #pragma unroll
    for (int rep = 0; rep < 8; rep++) {
        const int idx = rep * 256 + tid;
        const int c = idx >> 4, i4 = (idx & 15) * 4;
        const size_t base = ((size_t)b * C_ + c0 + c) * N_ + i0 + i4;
        const float4 xv = *(const float4*)(x + base);
        const float4 ov = *(const float4*)&sO[(size_t)c * 68 + i4];
        float4 o;
        o.x = g * ov.x + xv.x; o.y = g * ov.y + xv.y;
        o.z = g * ov.z + xv.z; o.w = g * ov.w + xv.w;
        *(float4*)(out + base) = o;
    }
}

// ---------------------------------------------------------------------------
// Launch
// ---------------------------------------------------------------------------
extern "C" void kernel_launch(void* const* d_in, const int* in_sizes, int n_in,
                              void* d_out, int out_size)
{
    const float* x     = (const float*)d_in[0];
    const float* wq    = (const float*)d_in[1];
    const float* bq    = (const float*)d_in[2];
    const float* wk    = (const float*)d_in[3];
    const float* bk    = (const float*)d_in[4];
    const float* wv    = (const float*)d_in[5];
    const float* bv    = (const float*)d_in[6];
    const float* gamma = (const float*)d_in[7];
    float* out = (float*)d_out;

    __nv_bfloat16 *pxt, *pqt, *pkt, *pvbf, *pwvbf;
    cudaGetSymbolAddress((void**)&pxt,   g_xt);
    cudaGetSymbolAddress((void**)&pqt,   g_qt);
    cudaGetSymbolAddress((void**)&pkt,   g_kt);
    cudaGetSymbolAddress((void**)&pvbf,  g_vbf);
    cudaGetSymbolAddress((void**)&pwvbf, g_wvbf);

    static bool attr_set = false;
    if (!attr_set) {
        cudaFuncSetAttribute(flash_tc, cudaFuncAttributeMaxDynamicSharedMemorySize,
                             FL_SMEM);
        attr_set = true;
    }

    pack_x_kernel<<<dim3(N_ / 32, C_ / 32, B_), 256>>>(x, pxt);
    pack_w_kernel<<<(C_ * C_ + 255) / 256, 256>>>(wv, pwvbf, C_ * C_);

    projqk_kernel<<<dim3(N_ / 64, 1, B_), 256>>>(wq, bq, wk, bk, x, pqt, pkt);
    projv_tc<<<dim3(N_ / 128, C_ / 128, B_), 256>>>(pwvbf, bv, pxt, pvbf);

    flash_tc<<<dim3(C_ / 128, N_ / 64, B_), 256, FL_SMEM>>>(pqt, pkt, pvbf, x, gamma, out);
}